// round 14
// baseline (speedup 1.0000x reference)
#include <cuda_runtime.h>
#include <cuda_fp16.h>
#include <cstdint>

// Problem constants
#define BATCH 512
#define INF   4096
#define OUTF  4096

// Fused-dequant GEMM: CTA = 32 out-rows x 512 batch, K-chunk 64 W-elements.
#define KC 64
#define ITERS (INF / KC)          // 64
#define TN 32
#define NCTAS (OUTF / TN)         // 128

// smem layout (bytes): A stages 512 rows x 128B (SW128 XOR swizzle),
// B is a 4-slot ring of 32x128B fp16 tiles (SW128 XOR).
#define OFF_A0 0
#define OFF_A1 65536
#define OFF_B  131072             // + slot*4096, slots 0..3
#define SMEM_BYTES 147456

// Scratch (device global = sanctioned scratch)
__device__ __half g_x[(size_t)BATCH * INF];  // x in fp16 (4 MB)

// ---------------- PTX helpers (plain-sm_103 legal) ----------------
__device__ __forceinline__ uint32_t smem_u32(const void* p) {
    uint32_t a;
    asm("{ .reg .u64 t; cvta.to.shared.u64 t, %1; cvt.u32.u64 %0, t; }" : "=r"(a) : "l"(p));
    return a;
}

#define CP_ASYNC16(dst_smem, src_gmem) \
    asm volatile("cp.async.cg.shared.global [%0], [%1], 16;" \
                 :: "r"((uint32_t)(dst_smem)), "l"(src_gmem) : "memory")
#define CP_COMMIT() asm volatile("cp.async.commit_group;" ::: "memory")
#define CP_WAIT(n)  asm volatile("cp.async.wait_group %0;" :: "n"(n) : "memory")

#define LDSM_X4(r0, r1, r2, r3, addr) \
    asm volatile("ldmatrix.sync.aligned.m8n8.x4.shared.b16 {%0,%1,%2,%3}, [%4];" \
                 : "=r"(r0), "=r"(r1), "=r"(r2), "=r"(r3) : "r"(addr))

#define MMA_F16(d, a, b) \
    asm volatile( \
        "mma.sync.aligned.m16n8k16.row.col.f32.f16.f16.f32 " \
        "{%0,%1,%2,%3}, {%4,%5,%6,%7}, {%8,%9}, {%0,%1,%2,%3};" \
        : "+f"((d)[0]), "+f"((d)[1]), "+f"((d)[2]), "+f"((d)[3]) \
        : "r"((a)[0]), "r"((a)[1]), "r"((a)[2]), "r"((a)[3]), \
          "r"((b)[0]), "r"((b)[1]))

#define STS_B16(addr, h) \
    asm volatile("st.shared.b16 [%0], %1;" :: "r"(addr), "h"(h) : "memory")

__device__ __forceinline__ float scale_from_exponent(const int* e) {
    int iv = *e;
    if (iv > -1000000 && iv < 1000000) return exp2f((float)iv);
    return exp2f(__int_as_float(iv));
}

// ---------------- kernel 0: convert x to fp16 ----------------
__global__ void __launch_bounds__(256) conv_x_kernel(const float* __restrict__ xf)
{
    const size_t base = (size_t)blockIdx.x * 2048 + threadIdx.x;
    #pragma unroll
    for (int i = 0; i < 8; ++i) {
        size_t idx = base + i * 256;
        g_x[idx] = __float2half_rn(xf[idx]);
    }
}

// ---------------- fused dequant + GEMM: y = x @ (U@t).T + b ----------------
// CTA bid owns out-rows [bid*32, bid*32+32), all 512 batch rows.
// Warp w (0..7) owns batch rows [w*64, w*64+64).
__global__ void __launch_bounds__(256, 1) fused_gemm(
    const float4* __restrict__ U4,   // one float4 per W element, row-major [OUTF, INF]
    const float* __restrict__ q,
    const int* __restrict__ e,
    const float* __restrict__ bias,
    float* __restrict__ out)
{
    extern __shared__ char smem[];
    const uint32_t sb = smem_u32(smem);
    const int tid  = threadIdx.x;
    const int wid  = tid >> 5;
    const int lane = tid & 31;
    const int g    = lane >> 2;
    const int t    = lane & 3;
    const int bid  = blockIdx.x;
    const int n0   = bid * TN;

    const float sc = scale_from_exponent(e) * (1.0f / 7.0f);
    const float t0 = q[0] * sc, t1 = q[1] * sc, t2 = q[2] * sc, t3 = q[3] * sc;

    // per-thread U/B element mapping: id = j*256+tid, n = id>>6, k = id&63
    const int my_n = tid >> 6;          // base n for j=0 (n advances by 4 per j)
    const int my_k = tid & 63;
    // U gmem index for (j, chunk): (n0 + my_n + 4*j)*INF + chunk*KC + my_k
    const size_t u_base = (size_t)(n0 + my_n) * INF + my_k;
    // B STS address within slot for element j: n = my_n+4j, k = my_k
    uint32_t b_off[8];
    #pragma unroll
    for (int j = 0; j < 8; ++j) {
        int n = my_n + 4 * j, k = my_k;
        b_off[j] = (uint32_t)(n * 128 + (((k >> 3) ^ (n & 7)) << 4) + ((k & 7) << 1));
    }

    auto ldg_u = [&](int chunk, float4* u) {
        const size_t cb = u_base + (size_t)chunk * KC;
        #pragma unroll
        for (int j = 0; j < 8; ++j) u[j] = U4[cb + (size_t)(4 * j) * INF];
    };
    auto cvt1 = [&](const float4& v) -> unsigned short {
        return __half_as_ushort(__float2half_rn(
            fmaf(v.x, t0, fmaf(v.y, t1, fmaf(v.z, t2, v.w * t3)))));
    };

    // A chunk (warp-private rows): warp w fills rows w*64..w*64+63.
    auto issue_A = [&](int it) {
        const uint32_t Ast = sb + ((it & 1) ? OFF_A1 : OFF_A0);
        const size_t kbase = (size_t)it * KC;   // halves
        #pragma unroll
        for (int j = 0; j < 16; ++j) {
            int id = j * 32 + lane;             // 0..511 within warp
            int rl = id >> 3, u = id & 7;
            int r  = wid * 64 + rl;
            CP_ASYNC16(Ast + (uint32_t)(r * 128 + ((u ^ (r & 7)) << 4)),
                       g_x + (size_t)r * INF + kbase + u * 8);
        }
        CP_COMMIT();
    };

    // ---- prologue ----
    issue_A(0);
    issue_A(1);
    {   // dequant chunks 0,1 into B slots 0,1 (LDG both, overlap latency)
        float4 u0[8], u1[8];
        ldg_u(0, u0);
        ldg_u(1, u1);
        const uint32_t B0 = sb + OFF_B, B1 = sb + OFF_B + 4096;
        #pragma unroll
        for (int j = 0; j < 8; ++j) STS_B16(B0 + b_off[j], cvt1(u0[j]));
        #pragma unroll
        for (int j = 0; j < 8; ++j) STS_B16(B1 + b_off[j], cvt1(u1[j]));
    }
    __syncthreads();                      // publish B0, B1

    float acc[4][4][4];
    #pragma unroll
    for (int i = 0; i < 4; ++i)
        #pragma unroll
        for (int j = 0; j < 4; ++j)
            #pragma unroll
            for (int k = 0; k < 4; ++k) acc[i][j][k] = 0.f;

    // ldmatrix lane base addresses (SW128 XOR; k-step applied as XOR of ks*32B)
    const int row_a = wid * 64 + (lane & 15);
    const uint32_t a_base = (uint32_t)(row_a * 128 + (((lane >> 4) ^ (row_a & 7)) << 4));
    const int row_b = ((lane >> 4) << 3) + (lane & 7);
    const uint32_t b_base = (uint32_t)(row_b * 128 + ((((lane >> 3) & 1) ^ (row_b & 7)) << 4));

    float4 u[8];
    ldg_u(2, u);                          // U for dequant during iter 0

    #pragma unroll 1
    for (int it = 0; it < ITERS; ++it) {
        CP_WAIT(1);                       // A(it) complete (A(it+1) outstanding)
        if ((it & 1) == 0 && it) __syncthreads();   // publish B(it), B(it+1)

        const bool have = (it + 2 < ITERS);
        const uint32_t Bn = sb + OFF_B + (uint32_t)(((it + 2) & 3) << 12);
        const uint32_t Bcur = sb + OFF_B + (uint32_t)((it & 3) << 12);
        const uint32_t Ast = sb + ((it & 1) ? OFF_A1 : OFF_A0);

        #pragma unroll
        for (int ks = 0; ks < 4; ++ks) {
            const uint32_t kx = (uint32_t)ks << 5;   // XOR k-offset
            uint32_t a[4][4], b[4][2];
            #pragma unroll
            for (int mt = 0; mt < 4; ++mt) {
                LDSM_X4(a[mt][0], a[mt][1], a[mt][2], a[mt][3],
                        Ast + ((a_base + (uint32_t)(mt * 2048)) ^ kx));
            }
            #pragma unroll
            for (int np = 0; np < 2; ++np) {
                LDSM_X4(b[2 * np][0], b[2 * np][1], b[2 * np + 1][0], b[2 * np + 1][1],
                        Bcur + ((b_base + (uint32_t)(np * 2048)) ^ kx));
            }
            #pragma unroll
            for (int mt = 0; mt < 4; ++mt)
                #pragma unroll
                for (int nt = 0; nt < 4; ++nt)
                    MMA_F16(acc[mt][nt], a[mt], b[nt]);

            // interleaved dequant of chunk it+2: 2 elements per ks step
            if (have) {
                STS_B16(Bn + b_off[ks * 2],     cvt1(u[ks * 2]));
                STS_B16(Bn + b_off[ks * 2 + 1], cvt1(u[ks * 2 + 1]));
            }
        }

        if (it + 3 < ITERS) ldg_u(it + 3, u);  // U for next iteration's dequant
        if (it + 2 < ITERS) issue_A(it + 2);   // warp-private A refill
        else CP_COMMIT();                       // keep group counting uniform
    }

    // ---- epilogue: registers -> gmem with fused bias, float2 stores ----
    #pragma unroll
    for (int nt = 0; nt < 4; ++nt) {
        const int n = n0 + nt * 8 + 2 * t;
        const float b0 = bias[n], b1 = bias[n + 1];
        #pragma unroll
        for (int mt = 0; mt < 4; ++mt) {
            const int m = wid * 64 + mt * 16 + g;
            float2 lo = make_float2(acc[mt][nt][0] + b0, acc[mt][nt][1] + b1);
            float2 hi = make_float2(acc[mt][nt][2] + b0, acc[mt][nt][3] + b1);
            *reinterpret_cast<float2*>(out + (size_t)m * OUTF + n) = lo;
            *reinterpret_cast<float2*>(out + (size_t)(m + 8) * OUTF + n) = hi;
        }
    }
}

// ---------------- launch ----------------
extern "C" void kernel_launch(void* const* d_in, const int* in_sizes, int n_in,
                              void* d_out, int out_size)
{
    const float* x = (const float*)d_in[0];   // [512, 4096]
    const float* U = (const float*)d_in[1];   // [4096*4096, 4]
    const float* q = (const float*)d_in[2];   // [4]
    const float* b = (const float*)d_in[3];   // [4096]
    const int*   e = (const int*)d_in[4];     // exponent scalar

    cudaFuncSetAttribute(fused_gemm,
                         cudaFuncAttributeMaxDynamicSharedMemorySize, SMEM_BYTES);

    conv_x_kernel<<<1024, 256>>>(x);
    fused_gemm<<<NCTAS, 256, SMEM_BYTES>>>((const float4*)U, q, e, b, (float*)d_out);
}

// round 16
// speedup vs baseline: 1.0873x; 1.0873x over previous
#include <cuda_runtime.h>
#include <cuda_fp16.h>
#include <cstdint>

// Problem constants
#define BATCH 512
#define INF   4096
#define OUTF  4096

// Fused-dequant GEMM: CTA = 32 out-rows x 512 batch, K-chunk 64 W-elements.
// 512 threads: 16 warps x 32 m-rows (4 warps per SMSP for tensor-pipe feed).
#define KC 64
#define ITERS (INF / KC)          // 64
#define TN 32
#define NCTAS (OUTF / TN)         // 128
#define THREADS 512

// smem layout (bytes): A stages 512 rows x 128B (SW128 XOR swizzle),
// B is a 4-slot ring of 32x128B fp16 tiles (SW128 XOR). Slot s at OFF_B + s*4096.
#define OFF_A0 0
#define OFF_A1 65536
#define OFF_B  131072
#define SMEM_BYTES 147456

// Scratch (device global = sanctioned scratch)
__device__ __half g_x[(size_t)BATCH * INF];  // x in fp16 (4 MB)

// ---------------- PTX helpers (plain-sm_103 legal) ----------------
__device__ __forceinline__ uint32_t smem_u32(const void* p) {
    uint32_t a;
    asm("{ .reg .u64 t; cvta.to.shared.u64 t, %1; cvt.u32.u64 %0, t; }" : "=r"(a) : "l"(p));
    return a;
}

#define CP_ASYNC16(dst_smem, src_gmem) \
    asm volatile("cp.async.cg.shared.global [%0], [%1], 16;" \
                 :: "r"((uint32_t)(dst_smem)), "l"(src_gmem) : "memory")
#define CP_COMMIT() asm volatile("cp.async.commit_group;" ::: "memory")
#define CP_WAIT(n)  asm volatile("cp.async.wait_group %0;" :: "n"(n) : "memory")

#define LDSM_X4(r0, r1, r2, r3, addr) \
    asm volatile("ldmatrix.sync.aligned.m8n8.x4.shared.b16 {%0,%1,%2,%3}, [%4];" \
                 : "=r"(r0), "=r"(r1), "=r"(r2), "=r"(r3) : "r"(addr))

#define MMA_F16(d, a, b) \
    asm volatile( \
        "mma.sync.aligned.m16n8k16.row.col.f32.f16.f16.f32 " \
        "{%0,%1,%2,%3}, {%4,%5,%6,%7}, {%8,%9}, {%0,%1,%2,%3};" \
        : "+f"((d)[0]), "+f"((d)[1]), "+f"((d)[2]), "+f"((d)[3]) \
        : "r"((a)[0]), "r"((a)[1]), "r"((a)[2]), "r"((a)[3]), \
          "r"((b)[0]), "r"((b)[1]))

#define STS_B16(addr, h) \
    asm volatile("st.shared.b16 [%0], %1;" :: "r"(addr), "h"(h) : "memory")

__device__ __forceinline__ float scale_from_exponent(const int* e) {
    int iv = *e;
    if (iv > -1000000 && iv < 1000000) return exp2f((float)iv);
    return exp2f(__int_as_float(iv));
}

// ---------------- kernel 0: convert x to fp16 ----------------
__global__ void __launch_bounds__(256) conv_x_kernel(const float* __restrict__ xf)
{
    const size_t base = (size_t)blockIdx.x * 2048 + threadIdx.x;
    #pragma unroll
    for (int i = 0; i < 8; ++i) {
        size_t idx = base + i * 256;
        g_x[idx] = __float2half_rn(xf[idx]);
    }
}

// ---------------- fused dequant + GEMM: y = x @ (U@t).T + b ----------------
// CTA bid owns out-rows [bid*32, bid*32+32), all 512 batch rows.
// Warp w (0..15) owns batch rows [w*32, w*32+32).
__global__ void __launch_bounds__(THREADS, 1) fused_gemm(
    const float4* __restrict__ U4,   // one float4 per W element, row-major [OUTF, INF]
    const float* __restrict__ q,
    const int* __restrict__ e,
    const float* __restrict__ bias,
    float* __restrict__ out)
{
    extern __shared__ char smem[];
    const uint32_t sb = smem_u32(smem);
    const int tid  = threadIdx.x;
    const int wid  = tid >> 5;
    const int lane = tid & 31;
    const int g    = lane >> 2;
    const int t    = lane & 3;
    const int bid  = blockIdx.x;
    const int n0   = bid * TN;

    const float sc = scale_from_exponent(e) * (1.0f / 7.0f);
    const float t0 = q[0] * sc, t1 = q[1] * sc, t2 = q[2] * sc, t3 = q[3] * sc;

    // per-thread U/B element mapping: id = j*512+tid, n = id>>6 (0..31), k = id&63
    // j advances n by 8 (4 elements per thread per chunk)
    const int my_n = tid >> 6;
    const int my_k = tid & 63;
    const size_t u_base = (size_t)(n0 + my_n) * INF + my_k;
    uint32_t b_off[4];
    #pragma unroll
    for (int j = 0; j < 4; ++j) {
        int n = my_n + 8 * j, k = my_k;
        b_off[j] = (uint32_t)(n * 128 + (((k >> 3) ^ (n & 7)) << 4) + ((k & 7) << 1));
    }

    auto ldg_u = [&](int chunk, float4* u) {
        const size_t cb = u_base + (size_t)chunk * KC;
        #pragma unroll
        for (int j = 0; j < 4; ++j) u[j] = U4[cb + (size_t)(8 * j) * INF];
    };
    auto cvt1 = [&](const float4& v) -> unsigned short {
        return __half_as_ushort(__float2half_rn(
            fmaf(v.x, t0, fmaf(v.y, t1, fmaf(v.z, t2, v.w * t3)))));
    };

    // A chunk (warp-private rows): warp w fills rows w*32..w*32+31 (8 cp.async/thread).
    auto issue_A = [&](int it) {
        const uint32_t Ast = sb + ((it & 1) ? OFF_A1 : OFF_A0);
        const size_t kbase = (size_t)it * KC;   // halves
        #pragma unroll
        for (int j = 0; j < 8; ++j) {
            int id = j * 32 + lane;             // 0..255 within warp
            int rl = id >> 3, u = id & 7;
            int r  = wid * 32 + rl;
            CP_ASYNC16(Ast + (uint32_t)(r * 128 + ((u ^ (r & 7)) << 4)),
                       g_x + (size_t)r * INF + kbase + u * 8);
        }
        CP_COMMIT();
    };

    // ---- prologue ----
    issue_A(0);
    issue_A(1);
    {   // dequant chunks 0,1 into B slots 0,1 (LDG both, overlap latency)
        float4 u0[4], u1[4];
        ldg_u(0, u0);
        ldg_u(1, u1);
        const uint32_t B0 = sb + OFF_B, B1 = sb + OFF_B + 4096;
        #pragma unroll
        for (int j = 0; j < 4; ++j) STS_B16(B0 + b_off[j], cvt1(u0[j]));
        #pragma unroll
        for (int j = 0; j < 4; ++j) STS_B16(B1 + b_off[j], cvt1(u1[j]));
    }
    __syncthreads();                      // publish B0, B1

    float acc[2][4][4];
    #pragma unroll
    for (int i = 0; i < 2; ++i)
        #pragma unroll
        for (int j = 0; j < 4; ++j)
            #pragma unroll
            for (int k = 0; k < 4; ++k) acc[i][j][k] = 0.f;

    // ldmatrix lane base addresses (SW128 XOR; k-step applied as XOR of ks*32B)
    const int row_a = wid * 32 + (lane & 15);
    const uint32_t a_base = (uint32_t)(row_a * 128 + (((lane >> 4) ^ (row_a & 7)) << 4));
    const int row_b = ((lane >> 4) << 3) + (lane & 7);
    const uint32_t b_base = (uint32_t)(row_b * 128 + ((((lane >> 3) & 1) ^ (row_b & 7)) << 4));

    float4 u[4];
    ldg_u(2, u);                          // U for dequant during iter 0

    #pragma unroll 1
    for (int it = 0; it < ITERS; ++it) {
        CP_WAIT(1);                       // A(it) complete (A(it+1) outstanding)
        __syncthreads();                  // publish B(it+1) writes from prev iter; A slot safe

        const bool have = (it + 2 < ITERS);
        const uint32_t Bn   = sb + OFF_B + (uint32_t)(((it + 2) & 3) << 12);  // 4-slot ring
        const uint32_t Bcur = sb + OFF_B + (uint32_t)((it & 3) << 12);
        const uint32_t Ast  = sb + ((it & 1) ? OFF_A1 : OFF_A0);

        #pragma unroll
        for (int ks = 0; ks < 4; ++ks) {
            const uint32_t kx = (uint32_t)ks << 5;   // XOR k-offset
            uint32_t a[2][4], b[4][2];
            #pragma unroll
            for (int mt = 0; mt < 2; ++mt) {
                LDSM_X4(a[mt][0], a[mt][1], a[mt][2], a[mt][3],
                        Ast + ((a_base + (uint32_t)(mt * 2048)) ^ kx));
            }
            #pragma unroll
            for (int np = 0; np < 2; ++np) {
                LDSM_X4(b[2 * np][0], b[2 * np][1], b[2 * np + 1][0], b[2 * np + 1][1],
                        Bcur + ((b_base + (uint32_t)(np * 2048)) ^ kx));
            }
            #pragma unroll
            for (int mt = 0; mt < 2; ++mt)
                #pragma unroll
                for (int nt = 0; nt < 4; ++nt)
                    MMA_F16(acc[mt][nt], a[mt], b[nt]);

            // interleaved dequant of chunk it+2 into slot (it+2)&3:
            // that slot's last readers (MMA of it-2) finished 2 barriers ago.
            if (have) STS_B16(Bn + b_off[ks], cvt1(u[ks]));
        }

        if (it + 3 < ITERS) ldg_u(it + 3, u);  // U for next iteration's dequant
        if (it + 2 < ITERS) issue_A(it + 2);   // warp-private A refill (this warp's reads done)
        else CP_COMMIT();                       // keep group counting uniform
    }

    // ---- epilogue: registers -> gmem with fused bias, float2 stores ----
    #pragma unroll
    for (int nt = 0; nt < 4; ++nt) {
        const int n = n0 + nt * 8 + 2 * t;
        const float b0 = bias[n], b1 = bias[n + 1];
        #pragma unroll
        for (int mt = 0; mt < 2; ++mt) {
            const int m = wid * 32 + mt * 16 + g;
            float2 lo = make_float2(acc[mt][nt][0] + b0, acc[mt][nt][1] + b1);
            float2 hi = make_float2(acc[mt][nt][2] + b0, acc[mt][nt][3] + b1);
            *reinterpret_cast<float2*>(out + (size_t)m * OUTF + n) = lo;
            *reinterpret_cast<float2*>(out + (size_t)(m + 8) * OUTF + n) = hi;
        }
    }
}

// ---------------- launch ----------------
extern "C" void kernel_launch(void* const* d_in, const int* in_sizes, int n_in,
                              void* d_out, int out_size)
{
    const float* x = (const float*)d_in[0];   // [512, 4096]
    const float* U = (const float*)d_in[1];   // [4096*4096, 4]
    const float* q = (const float*)d_in[2];   // [4]
    const float* b = (const float*)d_in[3];   // [4096]
    const int*   e = (const int*)d_in[4];     // exponent scalar

    cudaFuncSetAttribute(fused_gemm,
                         cudaFuncAttributeMaxDynamicSharedMemorySize, SMEM_BYTES);

    conv_x_kernel<<<1024, 256>>>(x);
    fused_gemm<<<NCTAS, THREADS, SMEM_BYTES>>>((const float4*)U, q, e, b, (float*)d_out);
}

// round 17
// speedup vs baseline: 1.0877x; 1.0004x over previous
#include <cuda_runtime.h>
#include <cuda_fp16.h>
#include <cstdint>

// Problem constants
#define BATCH 512
#define INF   4096
#define OUTF  4096

// Fused conv + dequant + GEMM: CTA = 32 out-rows x 512 batch, K-chunk 64.
// 512 threads: 16 warps x 32 m-rows (4 warps per SMSP for tensor-pipe feed).
#define KC 64
#define ITERS (INF / KC)          // 64
#define TN 32
#define NCTAS (OUTF / TN)         // 128
#define THREADS 512

// smem layout (bytes): A stages 512 rows x 128B (SW128 XOR swizzle),
// B is a 4-slot ring of 32x128B fp16 tiles (SW128 XOR). Slot s at OFF_B + s*4096.
#define OFF_A0 0
#define OFF_A1 65536
#define OFF_B  131072
#define SMEM_BYTES 147456

// Scratch (device global = sanctioned scratch)
__device__ __half g_x[(size_t)BATCH * INF];  // x in fp16 (4 MB)
__device__ int    g_sync;                    // monotonic epoch gate counter

// ---------------- PTX helpers (plain-sm_103 legal) ----------------
__device__ __forceinline__ uint32_t smem_u32(const void* p) {
    uint32_t a;
    asm("{ .reg .u64 t; cvta.to.shared.u64 t, %1; cvt.u32.u64 %0, t; }" : "=r"(a) : "l"(p));
    return a;
}

#define CP_ASYNC16(dst_smem, src_gmem) \
    asm volatile("cp.async.cg.shared.global [%0], [%1], 16;" \
                 :: "r"((uint32_t)(dst_smem)), "l"(src_gmem) : "memory")
#define CP_COMMIT() asm volatile("cp.async.commit_group;" ::: "memory")
#define CP_WAIT(n)  asm volatile("cp.async.wait_group %0;" :: "n"(n) : "memory")

#define LDSM_X4(r0, r1, r2, r3, addr) \
    asm volatile("ldmatrix.sync.aligned.m8n8.x4.shared.b16 {%0,%1,%2,%3}, [%4];" \
                 : "=r"(r0), "=r"(r1), "=r"(r2), "=r"(r3) : "r"(addr))

#define MMA_F16(d, a, b) \
    asm volatile( \
        "mma.sync.aligned.m16n8k16.row.col.f32.f16.f16.f32 " \
        "{%0,%1,%2,%3}, {%4,%5,%6,%7}, {%8,%9}, {%0,%1,%2,%3};" \
        : "+f"((d)[0]), "+f"((d)[1]), "+f"((d)[2]), "+f"((d)[3]) \
        : "r"((a)[0]), "r"((a)[1]), "r"((a)[2]), "r"((a)[3]), \
          "r"((b)[0]), "r"((b)[1]))

#define STS_B16(addr, h) \
    asm volatile("st.shared.b16 [%0], %1;" :: "r"(addr), "h"(h) : "memory")

__device__ __forceinline__ int ld_acquire(const int* p) {
    int v;
    asm volatile("ld.global.acquire.gpu.b32 %0, [%1];" : "=r"(v) : "l"(p) : "memory");
    return v;
}

__device__ __forceinline__ float scale_from_exponent(const int* e) {
    int iv = *e;
    if (iv > -1000000 && iv < 1000000) return exp2f((float)iv);
    return exp2f(__int_as_float(iv));
}

// ---------------- fused conv + dequant + GEMM: y = x @ (U@t).T + b ----------------
// CTA bid owns out-rows [bid*32, bid*32+32), all 512 batch rows.
// Warp w (0..15) owns batch rows [w*32, w*32+32).
__global__ void __launch_bounds__(THREADS, 1) fused_gemm(
    const float* __restrict__ xf,    // [512, 4096] fp32
    const float4* __restrict__ U4,   // one float4 per W element, row-major [OUTF, INF]
    const float* __restrict__ q,
    const int* __restrict__ e,
    const float* __restrict__ bias,
    float* __restrict__ out)
{
    extern __shared__ char smem[];
    const uint32_t sb = smem_u32(smem);
    const int tid  = threadIdx.x;
    const int wid  = tid >> 5;
    const int lane = tid & 31;
    const int g    = lane >> 2;
    const int t    = lane & 3;
    const int bid  = blockIdx.x;
    const int n0   = bid * TN;

    // ===== phase 0: convert this CTA's 1/128 slice of x to fp16 =====
    {
        const float4* x4 = reinterpret_cast<const float4*>(xf);
        uint2* gx2 = reinterpret_cast<uint2*>(g_x);
        const int base = bid * 4096;                 // float4 index base
        #pragma unroll
        for (int j = 0; j < 8; ++j) {
            int idx = base + j * 512 + tid;
            float4 v = x4[idx];
            __half2 lo = __floats2half2_rn(v.x, v.y);
            __half2 hi = __floats2half2_rn(v.z, v.w);
            gx2[idx] = make_uint2(*reinterpret_cast<uint32_t*>(&lo),
                                  *reinterpret_cast<uint32_t*>(&hi));
        }
    }
    __threadfence();
    __syncthreads();
    if (tid == 0) {
        int old = atomicAdd(&g_sync, 1);
        int target = (old / NCTAS + 1) * NCTAS;      // this replay's epoch boundary
        while (ld_acquire(&g_sync) < target) __nanosleep(64);
    }
    __syncthreads();                                 // all of g_x valid

    // ===== phase 1: fused dequant + GEMM (identical to R16) =====
    const float sc = scale_from_exponent(e) * (1.0f / 7.0f);
    const float t0 = q[0] * sc, t1 = q[1] * sc, t2 = q[2] * sc, t3 = q[3] * sc;

    const int my_n = tid >> 6;
    const int my_k = tid & 63;
    const size_t u_base = (size_t)(n0 + my_n) * INF + my_k;
    uint32_t b_off[4];
    #pragma unroll
    for (int j = 0; j < 4; ++j) {
        int n = my_n + 8 * j, k = my_k;
        b_off[j] = (uint32_t)(n * 128 + (((k >> 3) ^ (n & 7)) << 4) + ((k & 7) << 1));
    }

    auto ldg_u = [&](int chunk, float4* u) {
        const size_t cb = u_base + (size_t)chunk * KC;
        #pragma unroll
        for (int j = 0; j < 4; ++j) u[j] = U4[cb + (size_t)(8 * j) * INF];
    };
    auto cvt1 = [&](const float4& v) -> unsigned short {
        return __half_as_ushort(__float2half_rn(
            fmaf(v.x, t0, fmaf(v.y, t1, fmaf(v.z, t2, v.w * t3)))));
    };

    auto issue_A = [&](int it) {
        const uint32_t Ast = sb + ((it & 1) ? OFF_A1 : OFF_A0);
        const size_t kbase = (size_t)it * KC;   // halves
        #pragma unroll
        for (int j = 0; j < 8; ++j) {
            int id = j * 32 + lane;             // 0..255 within warp
            int rl = id >> 3, u = id & 7;
            int r  = wid * 32 + rl;
            CP_ASYNC16(Ast + (uint32_t)(r * 128 + ((u ^ (r & 7)) << 4)),
                       g_x + (size_t)r * INF + kbase + u * 8);
        }
        CP_COMMIT();
    };

    // ---- prologue ----
    issue_A(0);
    issue_A(1);
    {   // dequant chunks 0,1 into B slots 0,1
        float4 u0[4], u1[4];
        ldg_u(0, u0);
        ldg_u(1, u1);
        const uint32_t B0 = sb + OFF_B, B1 = sb + OFF_B + 4096;
        #pragma unroll
        for (int j = 0; j < 4; ++j) STS_B16(B0 + b_off[j], cvt1(u0[j]));
        #pragma unroll
        for (int j = 0; j < 4; ++j) STS_B16(B1 + b_off[j], cvt1(u1[j]));
    }
    __syncthreads();                      // publish B0, B1

    float acc[2][4][4];
    #pragma unroll
    for (int i = 0; i < 2; ++i)
        #pragma unroll
        for (int j = 0; j < 4; ++j)
            #pragma unroll
            for (int k = 0; k < 4; ++k) acc[i][j][k] = 0.f;

    const int row_a = wid * 32 + (lane & 15);
    const uint32_t a_base = (uint32_t)(row_a * 128 + (((lane >> 4) ^ (row_a & 7)) << 4));
    const int row_b = ((lane >> 4) << 3) + (lane & 7);
    const uint32_t b_base = (uint32_t)(row_b * 128 + ((((lane >> 3) & 1) ^ (row_b & 7)) << 4));

    float4 u[4];
    ldg_u(2, u);                          // U for dequant during iter 0

    #pragma unroll 1
    for (int it = 0; it < ITERS; ++it) {
        CP_WAIT(1);                       // A(it) complete (A(it+1) outstanding)
        __syncthreads();                  // publish B writes from prev iter; A slot safe

        const bool have = (it + 2 < ITERS);
        const uint32_t Bn   = sb + OFF_B + (uint32_t)(((it + 2) & 3) << 12);
        const uint32_t Bcur = sb + OFF_B + (uint32_t)((it & 3) << 12);
        const uint32_t Ast  = sb + ((it & 1) ? OFF_A1 : OFF_A0);

        #pragma unroll
        for (int ks = 0; ks < 4; ++ks) {
            const uint32_t kx = (uint32_t)ks << 5;   // XOR k-offset
            uint32_t a[2][4], b[4][2];
            #pragma unroll
            for (int mt = 0; mt < 2; ++mt) {
                LDSM_X4(a[mt][0], a[mt][1], a[mt][2], a[mt][3],
                        Ast + ((a_base + (uint32_t)(mt * 2048)) ^ kx));
            }
            #pragma unroll
            for (int np = 0; np < 2; ++np) {
                LDSM_X4(b[2 * np][0], b[2 * np][1], b[2 * np + 1][0], b[2 * np + 1][1],
                        Bcur + ((b_base + (uint32_t)(np * 2048)) ^ kx));
            }
            #pragma unroll
            for (int mt = 0; mt < 2; ++mt)
                #pragma unroll
                for (int nt = 0; nt < 4; ++nt)
                    MMA_F16(acc[mt][nt], a[mt], b[nt]);

            // interleaved dequant of chunk it+2 into slot (it+2)&3
            if (have) STS_B16(Bn + b_off[ks], cvt1(u[ks]));
        }

        if (it + 3 < ITERS) ldg_u(it + 3, u);  // U for next iteration's dequant
        if (it + 2 < ITERS) issue_A(it + 2);   // warp-private A refill
        else CP_COMMIT();                       // keep group counting uniform
    }

    // ---- epilogue: registers -> gmem with fused bias, float2 stores ----
    #pragma unroll
    for (int nt = 0; nt < 4; ++nt) {
        const int n = n0 + nt * 8 + 2 * t;
        const float b0 = bias[n], b1 = bias[n + 1];
        #pragma unroll
        for (int mt = 0; mt < 2; ++mt) {
            const int m = wid * 32 + mt * 16 + g;
            float2 lo = make_float2(acc[mt][nt][0] + b0, acc[mt][nt][1] + b1);
            float2 hi = make_float2(acc[mt][nt][2] + b0, acc[mt][nt][3] + b1);
            *reinterpret_cast<float2*>(out + (size_t)m * OUTF + n) = lo;
            *reinterpret_cast<float2*>(out + (size_t)(m + 8) * OUTF + n) = hi;
        }
    }
}

// ---------------- launch ----------------
extern "C" void kernel_launch(void* const* d_in, const int* in_sizes, int n_in,
                              void* d_out, int out_size)
{
    const float* x = (const float*)d_in[0];   // [512, 4096]
    const float* U = (const float*)d_in[1];   // [4096*4096, 4]
    const float* q = (const float*)d_in[2];   // [4]
    const float* b = (const float*)d_in[3];   // [4096]
    const int*   e = (const int*)d_in[4];     // exponent scalar

    cudaFuncSetAttribute(fused_gemm,
                         cudaFuncAttributeMaxDynamicSharedMemorySize, SMEM_BYTES);

    fused_gemm<<<NCTAS, THREADS, SMEM_BYTES>>>(
        x, (const float4*)U, q, e, b, (float*)d_out);
}